// round 1
// baseline (speedup 1.0000x reference)
#include <cuda_runtime.h>
#include <math.h>

#define N_NODESC 50000
#define N_EDGESC 640000
#define N_GRAPHSC 64
#define INF_C 8
#define HC 128

typedef unsigned long long ull;

// ---------------- scratch (device globals: no runtime allocation) ----------------
__device__ int   g_deg[N_NODESC];
__device__ int   g_off[N_NODESC + 1];
__device__ int   g_pos[N_NODESC];
__device__ int   g_srcs[N_EDGESC];
__device__ float g_agg8[N_NODESC * INF_C];
__device__ float g_hin[N_NODESC * HC];
__device__ float g_mid[N_NODESC * HC];
__device__ float g_h1[N_NODESC * HC];
__device__ float g_h2[N_NODESC * HC];
__device__ float g_h3[N_NODESC * HC];
__device__ float g_pooled[N_GRAPHSC * 3 * HC];

// ---------------- f32x2 helpers (Blackwell packed fp32) ----------------
__device__ __forceinline__ ull pack2(float x, float y) {
    ull r;
    asm("mov.b64 %0, {%1, %2};" : "=l"(r) : "f"(x), "f"(y));
    return r;
}
__device__ __forceinline__ void ffma2(ull& d, ull a, ull b) {
    asm("fma.rn.f32x2 %0, %1, %2, %3;" : "=l"(d) : "l"(a), "l"(b), "l"(d));
}
__device__ __forceinline__ float2 unpack2(ull p) {
    float2 f;
    asm("mov.b64 {%0, %1}, %2;" : "=f"(f.x), "=f"(f.y) : "l"(p));
    return f;
}

// ---------------- CSR build ----------------
__global__ void k_zero_deg() {
    int i = blockIdx.x * blockDim.x + threadIdx.x;
    if (i < N_NODESC) g_deg[i] = 0;
}

__global__ void k_hist(const int* __restrict__ ei) {
    int e = blockIdx.x * blockDim.x + threadIdx.x;
    if (e < N_EDGESC) {
        int d = ei[N_EDGESC + e];
        atomicAdd(&g_deg[d], 1);
    }
}

// single-block exclusive scan over g_deg -> g_off, g_pos
__global__ void k_scan() {
    __shared__ int warpsum[32];
    __shared__ int chunk_total;
    int tid = threadIdx.x, lane = tid & 31, wid = tid >> 5;
    int carry = 0;
    for (int base = 0; base < N_NODESC; base += 1024) {
        int i = base + tid;
        int v = (i < N_NODESC) ? g_deg[i] : 0;
        int incl = v;
        #pragma unroll
        for (int o = 1; o < 32; o <<= 1) {
            int t = __shfl_up_sync(0xffffffffu, incl, o);
            if (lane >= o) incl += t;
        }
        if (lane == 31) warpsum[wid] = incl;
        __syncthreads();
        if (wid == 0) {
            int s = warpsum[lane];
            int si = s;
            #pragma unroll
            for (int o = 1; o < 32; o <<= 1) {
                int t = __shfl_up_sync(0xffffffffu, si, o);
                if (lane >= o) si += t;
            }
            warpsum[lane] = si - s;          // exclusive warp prefix
            if (lane == 31) chunk_total = si;
        }
        __syncthreads();
        int excl = carry + warpsum[wid] + incl - v;
        if (i < N_NODESC) { g_off[i] = excl; g_pos[i] = excl; }
        carry += chunk_total;
        __syncthreads();
    }
    if (tid == 0) g_off[N_NODESC] = carry;
}

__global__ void k_fill(const int* __restrict__ ei) {
    int e = blockIdx.x * blockDim.x + threadIdx.x;
    if (e < N_EDGESC) {
        int s = ei[e];
        int d = ei[N_EDGESC + e];
        int p = atomicAdd(&g_pos[d], 1);
        g_srcs[p] = s;
    }
}

// ---------------- aggregation ----------------
// layer 1: 8-wide. one thread per (node, feature)
__global__ void k_agg8(const float* __restrict__ x) {
    int gid = blockIdx.x * blockDim.x + threadIdx.x;
    if (gid >= N_NODESC * INF_C) return;
    int n = gid >> 3;
    int f = gid & 7;
    float acc = x[n * INF_C + f];
    int s0 = g_off[n], s1 = g_off[n + 1];
    for (int j = s0; j < s1; j++) {
        acc += x[g_srcs[j] * INF_C + f];
    }
    g_agg8[gid] = acc;
}

// 128-wide: one warp per node, float4 per lane
__global__ void k_agg128(const float* __restrict__ xin, float* __restrict__ out) {
    int warp = (blockIdx.x * blockDim.x + threadIdx.x) >> 5;
    if (warp >= N_NODESC) return;
    int lane = threadIdx.x & 31;
    const float4* xi = (const float4*)xin;
    float4 acc = xi[warp * 32 + lane];
    float4 acc2 = make_float4(0.f, 0.f, 0.f, 0.f);
    int s0 = g_off[warp], s1 = g_off[warp + 1];
    int j = s0;
    for (; j + 1 < s1; j += 2) {
        int sA = g_srcs[j];
        int sB = g_srcs[j + 1];
        float4 vA = xi[sA * 32 + lane];
        float4 vB = xi[sB * 32 + lane];
        acc.x += vA.x; acc.y += vA.y; acc.z += vA.z; acc.w += vA.w;
        acc2.x += vB.x; acc2.y += vB.y; acc2.z += vB.z; acc2.w += vB.w;
    }
    if (j < s1) {
        int s = g_srcs[j];
        float4 v = xi[s * 32 + lane];
        acc.x += v.x; acc.y += v.y; acc.z += v.z; acc.w += v.w;
    }
    acc.x += acc2.x; acc.y += acc2.y; acc.z += acc2.z; acc.w += acc2.w;
    ((float4*)out)[warp * 32 + lane] = acc;
}

// ---------------- GEMMs ----------------
// K=8 first linear of layer 1: relu(A[M,8] @ W[8,128] + b)
__global__ void k_gemm8(const float* __restrict__ A, const float* __restrict__ W,
                        const float* __restrict__ bias, float* __restrict__ C, int M) {
    __shared__ float Ws[INF_C * HC];
    __shared__ float bs[HC];
    int tid = threadIdx.x;
    for (int i = tid; i < INF_C * HC; i += 256) Ws[i] = W[i];
    if (tid < HC) bs[tid] = bias[tid];
    __syncthreads();
    int warp = tid >> 5, lane = tid & 31;
    int row = blockIdx.x * 8 + warp;
    if (row >= M) return;
    float a[INF_C];
    #pragma unroll
    for (int k = 0; k < INF_C; k++) a[k] = A[row * INF_C + k];
    int c = lane * 4;
    float4 acc = make_float4(bs[c], bs[c + 1], bs[c + 2], bs[c + 3]);
    #pragma unroll
    for (int k = 0; k < INF_C; k++) {
        float4 w = *(const float4*)&Ws[k * HC + c];
        acc.x += a[k] * w.x; acc.y += a[k] * w.y;
        acc.z += a[k] * w.z; acc.w += a[k] * w.w;
    }
    acc.x = fmaxf(acc.x, 0.f); acc.y = fmaxf(acc.y, 0.f);
    acc.z = fmaxf(acc.z, 0.f); acc.w = fmaxf(acc.w, 0.f);
    *(float4*)&C[row * HC + c] = acc;
}

// K=128, N=128 GEMM with relu epilogue. 128x128 tile, BK=32, f32x2 packed FMA.
__global__ __launch_bounds__(256, 2)
void k_gemm128(const float* __restrict__ A, const float* __restrict__ W,
               const float* __restrict__ bias, float* __restrict__ C, int M) {
    __shared__ float As[128][36];   // [row][k], stride 36 (16B aligned)
    __shared__ float Bs[32][136];   // [k][n],  stride 136 (16B aligned)
    int tid = threadIdx.x;
    int tx = tid & 15, ty = tid >> 4;
    int row0 = blockIdx.x * 128;
    int r0 = ty * 8, c0 = tx * 8;

    ull acc[8][4];
    #pragma unroll
    for (int i = 0; i < 8; i++)
        #pragma unroll
        for (int j = 0; j < 4; j++) acc[i][j] = 0ull;

    for (int kt = 0; kt < 4; kt++) {
        // A tile: 128 rows x 32 k = 1024 float4, 4 per thread
        #pragma unroll
        for (int t = 0; t < 4; t++) {
            int idx = tid + t * 256;
            int ar = idx >> 3;
            int fq = idx & 7;
            int grow = row0 + ar;
            float4 v = make_float4(0.f, 0.f, 0.f, 0.f);
            if (grow < M) v = *(const float4*)&A[grow * 128 + kt * 32 + fq * 4];
            *(float4*)&As[ar][fq * 4] = v;
        }
        // B tile: 32 k-rows x 128 n
        #pragma unroll
        for (int t = 0; t < 4; t++) {
            int k = (tid >> 5) + t * 8;
            int n = (tid & 31) * 4;
            *(float4*)&Bs[k][n] = *(const float4*)&W[(kt * 32 + k) * 128 + n];
        }
        __syncthreads();
        #pragma unroll
        for (int k = 0; k < 32; k++) {
            float av[8];
            #pragma unroll
            for (int i = 0; i < 8; i++) av[i] = As[r0 + i][k];   // broadcast (2 addrs/warp)
            float4 b0 = *(const float4*)&Bs[k][c0];
            float4 b1 = *(const float4*)&Bs[k][c0 + 4];
            ull bb0 = pack2(b0.x, b0.y);
            ull bb1 = pack2(b0.z, b0.w);
            ull bb2 = pack2(b1.x, b1.y);
            ull bb3 = pack2(b1.z, b1.w);
            #pragma unroll
            for (int i = 0; i < 8; i++) {
                ull aa = pack2(av[i], av[i]);
                ffma2(acc[i][0], aa, bb0);
                ffma2(acc[i][1], aa, bb1);
                ffma2(acc[i][2], aa, bb2);
                ffma2(acc[i][3], aa, bb3);
            }
        }
        __syncthreads();
    }

    float bsv[8];
    #pragma unroll
    for (int j = 0; j < 8; j++) bsv[j] = __ldg(&bias[c0 + j]);
    #pragma unroll
    for (int i = 0; i < 8; i++) {
        int row = row0 + r0 + i;
        if (row < M) {
            float2 p0 = unpack2(acc[i][0]);
            float2 p1 = unpack2(acc[i][1]);
            float2 p2 = unpack2(acc[i][2]);
            float2 p3 = unpack2(acc[i][3]);
            float4 o0 = make_float4(fmaxf(p0.x + bsv[0], 0.f), fmaxf(p0.y + bsv[1], 0.f),
                                    fmaxf(p1.x + bsv[2], 0.f), fmaxf(p1.y + bsv[3], 0.f));
            float4 o1 = make_float4(fmaxf(p2.x + bsv[4], 0.f), fmaxf(p2.y + bsv[5], 0.f),
                                    fmaxf(p3.x + bsv[6], 0.f), fmaxf(p3.y + bsv[7], 0.f));
            *(float4*)&C[row * 128 + c0] = o0;
            *(float4*)&C[row * 128 + c0 + 4] = o1;
        }
    }
}

// ---------------- pooling ----------------
// grid (64 graphs, 3 segments), block 128. batch sorted -> binary search range.
__global__ void k_pool(const int* __restrict__ batch) {
    __shared__ int se[2];
    int gph = blockIdx.x, seg = blockIdx.y, tid = threadIdx.x;
    if (tid < 2) {
        int target = gph + tid;
        int lo = 0, hi = N_NODESC;
        while (lo < hi) {
            int mid = (lo + hi) >> 1;
            if (batch[mid] < target) lo = mid + 1; else hi = mid;
        }
        se[tid] = lo;
    }
    __syncthreads();
    const float* h = (seg == 0) ? g_h1 : ((seg == 1) ? g_h2 : g_h3);
    float acc = 0.f;
    int n = se[0], e = se[1];
    for (; n + 1 < e; n += 2) {
        acc += h[n * HC + tid];
        acc += h[(n + 1) * HC + tid];
    }
    if (n < e) acc += h[n * HC + tid];
    g_pooled[gph * (3 * HC) + seg * HC + tid] = acc;
}

// ---------------- classifier ----------------
__global__ void k_cls(const float* __restrict__ W1, const float* __restrict__ b1,
                      const float* __restrict__ bng, const float* __restrict__ bnb,
                      const float* __restrict__ bnm, const float* __restrict__ bnv,
                      const float* __restrict__ W2, const float* __restrict__ b2,
                      float* __restrict__ out) {
    __shared__ float ps[3 * HC];
    __shared__ float zs[2 * HC];
    int gph = blockIdx.x, tid = threadIdx.x;   // 256 threads
    for (int i = tid; i < 3 * HC; i += 256) ps[i] = g_pooled[gph * (3 * HC) + i];
    __syncthreads();
    float acc = b1[tid];
    for (int k = 0; k < 3 * HC; k++) acc += ps[k] * W1[k * 256 + tid];
    acc = (acc - bnm[tid]) * rsqrtf(bnv[tid] + 1e-5f) * bng[tid] + bnb[tid];
    acc = fmaxf(acc, 0.f);
    zs[tid] = acc;
    __syncthreads();
    if (tid < 4) {
        float s = b2[tid];
        for (int k = 0; k < 256; k++) s += zs[k] * W2[k * 4 + tid];
        out[gph * 4 + tid] = s;
    }
}

// ---------------- launch ----------------
extern "C" void kernel_launch(void* const* d_in, const int* in_sizes, int n_in,
                              void* d_out, int out_size) {
    const float* x   = (const float*)d_in[0];
    const int* ei    = (const int*)d_in[1];
    const int* batch = (const int*)d_in[2];
    const float* l1W1 = (const float*)d_in[3];
    const float* l1b1 = (const float*)d_in[4];
    const float* l1W2 = (const float*)d_in[5];
    const float* l1b2 = (const float*)d_in[6];
    const float* l2W1 = (const float*)d_in[7];
    const float* l2b1 = (const float*)d_in[8];
    const float* l2W2 = (const float*)d_in[9];
    const float* l2b2 = (const float*)d_in[10];
    const float* l3W1 = (const float*)d_in[11];
    const float* l3b1 = (const float*)d_in[12];
    const float* l3W2 = (const float*)d_in[13];
    const float* l3b2 = (const float*)d_in[14];
    const float* cW1  = (const float*)d_in[15];
    const float* cb1  = (const float*)d_in[16];
    const float* bng  = (const float*)d_in[17];
    const float* bnb  = (const float*)d_in[18];
    const float* bnm  = (const float*)d_in[19];
    const float* bnv  = (const float*)d_in[20];
    const float* cW2  = (const float*)d_in[21];
    const float* cb2  = (const float*)d_in[22];
    float* out = (float*)d_out;

    float *agg8, *hin, *mid, *h1, *h2, *h3;
    cudaGetSymbolAddress((void**)&agg8, g_agg8);
    cudaGetSymbolAddress((void**)&hin, g_hin);
    cudaGetSymbolAddress((void**)&mid, g_mid);
    cudaGetSymbolAddress((void**)&h1, g_h1);
    cudaGetSymbolAddress((void**)&h2, g_h2);
    cudaGetSymbolAddress((void**)&h3, g_h3);

    const int M = N_NODESC;
    // CSR build
    k_zero_deg<<<(N_NODESC + 255) / 256, 256>>>();
    k_hist<<<(N_EDGESC + 255) / 256, 256>>>(ei);
    k_scan<<<1, 1024>>>();
    k_fill<<<(N_EDGESC + 255) / 256, 256>>>(ei);

    int gemm_blocks = (M + 127) / 128;
    int agg_blocks = (M * 32 + 255) / 256;

    // layer 1
    k_agg8<<<(M * INF_C + 255) / 256, 256>>>(x);
    k_gemm8<<<(M + 7) / 8, 256>>>(agg8, l1W1, l1b1, mid, M);
    k_gemm128<<<gemm_blocks, 256>>>(mid, l1W2, l1b2, h1, M);
    // layer 2
    k_agg128<<<agg_blocks, 256>>>(h1, hin);
    k_gemm128<<<gemm_blocks, 256>>>(hin, l2W1, l2b1, mid, M);
    k_gemm128<<<gemm_blocks, 256>>>(mid, l2W2, l2b2, h2, M);
    // layer 3
    k_agg128<<<agg_blocks, 256>>>(h2, hin);
    k_gemm128<<<gemm_blocks, 256>>>(hin, l3W1, l3b1, mid, M);
    k_gemm128<<<gemm_blocks, 256>>>(mid, l3W2, l3b2, h3, M);
    // pool + classifier
    k_pool<<<dim3(N_GRAPHSC, 3), 128>>>(batch);
    k_cls<<<N_GRAPHSC, 256>>>(cW1, cb1, bng, bnb, bnm, bnv, cW2, cb2, out);
}

// round 3
// speedup vs baseline: 1.1320x; 1.1320x over previous
#include <cuda_runtime.h>
#include <math.h>

#define N_NODESC 50000
#define N_EDGESC 640000
#define N_GRAPHSC 64
#define INF_C 8
#define HC 128
#define ASTRIDE 132   // padded row stride (floats) for A/mid tile in smem

typedef unsigned long long ull;

// ---------------- scratch (device globals) ----------------
__device__ __align__(16) int   g_deg[N_NODESC];
__device__ __align__(16) int   g_off[N_NODESC + 1];
__device__ __align__(16) int   g_pos[N_NODESC];
__device__ __align__(16) int   g_srcs[N_EDGESC];
__device__ __align__(16) float g_h1[N_NODESC * HC];
__device__ __align__(16) float g_h2[N_NODESC * HC];
__device__ __align__(16) float g_pooled[N_GRAPHSC * 3 * HC];

// ---------------- f32x2 helpers ----------------
__device__ __forceinline__ ull pack2(float x, float y) {
    ull r;
    asm("mov.b64 %0, {%1, %2};" : "=l"(r) : "f"(x), "f"(y));
    return r;
}
__device__ __forceinline__ void ffma2(ull& d, ull a, ull b) {
    asm("fma.rn.f32x2 %0, %1, %2, %3;" : "=l"(d) : "l"(a), "l"(b), "l"(d));
}
__device__ __forceinline__ float2 unpack2(ull p) {
    float2 f;
    asm("mov.b64 {%0, %1}, %2;" : "=f"(f.x), "=f"(f.y) : "l"(p));
    return f;
}

// ---------------- CSR build ----------------
__global__ void k_init() {
    int i = blockIdx.x * blockDim.x + threadIdx.x;
    if (i < N_NODESC) g_deg[i] = 0;
    if (i < N_GRAPHSC * 3 * HC) g_pooled[i] = 0.f;
}

__global__ void k_hist(const int* __restrict__ ei) {
    int e = blockIdx.x * blockDim.x + threadIdx.x;
    if (e < N_EDGESC) atomicAdd(&g_deg[ei[N_EDGESC + e]], 1);
}

// single-block scan, 4 elems/thread per chunk (4096/chunk -> 13 chunks)
__global__ void k_scan() {
    __shared__ int wsum[32];
    __shared__ int ctot;
    int tid = threadIdx.x, lane = tid & 31, wid = tid >> 5;
    int carry = 0;
    for (int base = 0; base < N_NODESC; base += 4096) {
        int i = base + tid * 4;
        int4 v = make_int4(0, 0, 0, 0);
        if (i < N_NODESC) v = ((const int4*)g_deg)[base / 4 + tid];
        int s0 = v.x, s1 = s0 + v.y, s2 = s1 + v.z, s3 = s2 + v.w;
        int incl = s3;
        #pragma unroll
        for (int o = 1; o < 32; o <<= 1) {
            int t = __shfl_up_sync(0xffffffffu, incl, o);
            if (lane >= o) incl += t;
        }
        if (lane == 31) wsum[wid] = incl;
        __syncthreads();
        if (wid == 0) {
            int s = wsum[lane];
            int si = s;
            #pragma unroll
            for (int o = 1; o < 32; o <<= 1) {
                int t = __shfl_up_sync(0xffffffffu, si, o);
                if (lane >= o) si += t;
            }
            wsum[lane] = si - s;
            if (lane == 31) ctot = si;
        }
        __syncthreads();
        int excl = carry + wsum[wid] + incl - s3;   // exclusive base for this thread
        if (i < N_NODESC) {
            g_off[i] = excl;            g_pos[i] = excl;
            g_off[i + 1] = excl + s0;   g_pos[i + 1] = excl + s0;
            g_off[i + 2] = excl + s1;   g_pos[i + 2] = excl + s1;
            g_off[i + 3] = excl + s2;   g_pos[i + 3] = excl + s2;
        }
        carry += ctot;
        __syncthreads();
    }
    if (tid == 0) g_off[N_NODESC] = carry;
}

__global__ void k_fill(const int* __restrict__ ei) {
    int e = blockIdx.x * blockDim.x + threadIdx.x;
    if (e < N_EDGESC) {
        int s = ei[e];
        int d = ei[N_EDGESC + e];
        g_srcs[atomicAdd(&g_pos[d], 1)] = s;
    }
}

// ---------------- shared GEMM micro-kernel ----------------
// 128x128 output tile, 256 threads, micro 8 rows x (4 + 4 split) cols.
__device__ __forceinline__ void gemm_tile(const float* __restrict__ At, int astride,
                                          const float* __restrict__ Bs, int K,
                                          ull acc[8][4], int r0, int c0) {
    #pragma unroll 4
    for (int k = 0; k < K; k++) {
        float a[8];
        #pragma unroll
        for (int i = 0; i < 8; i++) a[i] = At[(r0 + i) * astride + k];
        float4 bl = *(const float4*)&Bs[k * 128 + c0];
        float4 bh = *(const float4*)&Bs[k * 128 + c0 + 64];
        ull b0 = pack2(bl.x, bl.y), b1p = pack2(bl.z, bl.w);
        ull b2p = pack2(bh.x, bh.y), b3p = pack2(bh.z, bh.w);
        #pragma unroll
        for (int i = 0; i < 8; i++) {
            ull aa = pack2(a[i], a[i]);
            ffma2(acc[i][0], aa, b0);
            ffma2(acc[i][1], aa, b1p);
            ffma2(acc[i][2], aa, b2p);
            ffma2(acc[i][3], aa, b3p);
        }
    }
}

__device__ __forceinline__ void epi_relu(const ull acc[4], const float* __restrict__ bias,
                                         int c0, float4& lo, float4& hi) {
    float4 bl = *(const float4*)&bias[c0];
    float4 bh = *(const float4*)&bias[c0 + 64];
    float2 p0 = unpack2(acc[0]), p1 = unpack2(acc[1]);
    float2 p2 = unpack2(acc[2]), p3 = unpack2(acc[3]);
    lo = make_float4(fmaxf(p0.x + bl.x, 0.f), fmaxf(p0.y + bl.y, 0.f),
                     fmaxf(p1.x + bl.z, 0.f), fmaxf(p1.y + bl.w, 0.f));
    hi = make_float4(fmaxf(p2.x + bh.x, 0.f), fmaxf(p2.y + bh.y, 0.f),
                     fmaxf(p3.x + bh.z, 0.f), fmaxf(p3.y + bh.w, 0.f));
}

// pooling epilogue: h tile resident in As (stride ASTRIDE), batchS has graph ids (-1 pad)
__device__ __forceinline__ void pool_tile(const float* __restrict__ As,
                                          const int* __restrict__ batchS,
                                          int seg, int tid) {
    int col = tid & 127;
    int h0 = (tid >> 7) * 64;
    float acc = 0.f;
    int cur = -1;
    for (int rr = h0; rr < h0 + 64; rr++) {
        int g = batchS[rr];
        if (g < 0) break;
        if (g != cur) {
            if (cur >= 0) atomicAdd(&g_pooled[cur * (3 * HC) + seg * HC + col], acc);
            acc = 0.f;
            cur = g;
        }
        acc += As[rr * ASTRIDE + col];
    }
    if (cur >= 0) atomicAdd(&g_pooled[cur * (3 * HC) + seg * HC + col], acc);
}

// ---------------- fused GIN layer (layers 2,3): agg + MLP + pool ----------------
__global__ __launch_bounds__(256, 1)
void k_layer(const float* __restrict__ hin, const float* __restrict__ W1,
             const float* __restrict__ b1v, const float* __restrict__ W2,
             const float* __restrict__ b2v, float* __restrict__ hout,
             const int* __restrict__ batch, int seg, int write_out) {
    extern __shared__ float sm[];
    float* As  = sm;                      // 128 x ASTRIDE (agg -> mid -> h)
    float* B1s = sm + 128 * ASTRIDE;      // 128 x 128
    float* B2s = B1s + 128 * 128;         // 128 x 128
    __shared__ int batchS[128];

    int tid = threadIdx.x, lane = tid & 31, wid = tid >> 5;
    int row0 = blockIdx.x * 128;

    // stage weights
    #pragma unroll
    for (int t = 0; t < 16; t++) {
        int idx = tid + t * 256;
        ((float4*)B1s)[idx] = ((const float4*)W1)[idx];
        ((float4*)B2s)[idx] = ((const float4*)W2)[idx];
    }
    if (tid < 128) {
        int row = row0 + tid;
        batchS[tid] = (row < N_NODESC) ? batch[row] : -1;
    }

    // aggregation: warp per row, float4 per lane
    const float4* xi = (const float4*)hin;
    for (int rr = wid; rr < 128; rr += 8) {
        int row = row0 + rr;
        float4 acc = make_float4(0.f, 0.f, 0.f, 0.f);
        if (row < N_NODESC) {
            acc = xi[row * 32 + lane];
            float4 acc2 = make_float4(0.f, 0.f, 0.f, 0.f);
            int s0 = g_off[row], s1 = g_off[row + 1];
            int j = s0;
            for (; j + 1 < s1; j += 2) {
                float4 vA = xi[g_srcs[j] * 32 + lane];
                float4 vB = xi[g_srcs[j + 1] * 32 + lane];
                acc.x += vA.x; acc.y += vA.y; acc.z += vA.z; acc.w += vA.w;
                acc2.x += vB.x; acc2.y += vB.y; acc2.z += vB.z; acc2.w += vB.w;
            }
            if (j < s1) {
                float4 v = xi[g_srcs[j] * 32 + lane];
                acc.x += v.x; acc.y += v.y; acc.z += v.z; acc.w += v.w;
            }
            acc.x += acc2.x; acc.y += acc2.y; acc.z += acc2.z; acc.w += acc2.w;
        }
        *(float4*)&As[rr * ASTRIDE + lane * 4] = acc;
    }
    __syncthreads();

    int tx = tid & 15, ty = tid >> 4;
    int r0 = ty * 8, c0 = tx * 4;

    // GEMM1: mid = relu(agg @ W1 + b1)
    ull acc[8][4];
    #pragma unroll
    for (int i = 0; i < 8; i++)
        #pragma unroll
        for (int j = 0; j < 4; j++) acc[i][j] = 0ull;
    gemm_tile(As, ASTRIDE, B1s, 128, acc, r0, c0);
    __syncthreads();    // all reads of As(agg) done
    #pragma unroll
    for (int i = 0; i < 8; i++) {
        float4 lo, hi;
        epi_relu(acc[i], b1v, c0, lo, hi);
        *(float4*)&As[(r0 + i) * ASTRIDE + c0] = lo;
        *(float4*)&As[(r0 + i) * ASTRIDE + c0 + 64] = hi;
    }
    __syncthreads();

    // GEMM2: h = relu(mid @ W2 + b2)
    #pragma unroll
    for (int i = 0; i < 8; i++)
        #pragma unroll
        for (int j = 0; j < 4; j++) acc[i][j] = 0ull;
    gemm_tile(As, ASTRIDE, B2s, 128, acc, r0, c0);
    __syncthreads();    // all reads of As(mid) done
    #pragma unroll
    for (int i = 0; i < 8; i++) {
        float4 lo, hi;
        epi_relu(acc[i], b2v, c0, lo, hi);
        int rr = r0 + i, row = row0 + rr;
        *(float4*)&As[rr * ASTRIDE + c0] = lo;
        *(float4*)&As[rr * ASTRIDE + c0 + 64] = hi;
        if (write_out && row < N_NODESC) {
            *(float4*)&hout[row * HC + c0] = lo;
            *(float4*)&hout[row * HC + c0 + 64] = hi;
        }
    }
    __syncthreads();

    pool_tile(As, batchS, seg, tid);
}

// ---------------- fused layer 1: agg8 + MLP(8->128->128) + pool ----------------
__global__ __launch_bounds__(256, 1)
void k_layer1(const float* __restrict__ x, const float* __restrict__ W1,
              const float* __restrict__ b1v, const float* __restrict__ W2,
              const float* __restrict__ b2v, float* __restrict__ hout,
              const int* __restrict__ batch) {
    extern __shared__ float sm[];
    float* As  = sm;                      // 128 x ASTRIDE (mid -> h)
    float* B2s = sm + 128 * ASTRIDE;      // 128 x 128
    float* A8  = B2s + 128 * 128;         // 128 x 8
    float* B8  = A8 + 128 * 8;            // 8 x 128
    __shared__ int batchS[128];

    int tid = threadIdx.x;
    int row0 = blockIdx.x * 128;

    // stage weights
    ((float4*)B8)[tid] = ((const float4*)W1)[tid];   // 256 float4 = 1024 floats
    #pragma unroll
    for (int t = 0; t < 16; t++) {
        int idx = tid + t * 256;
        ((float4*)B2s)[idx] = ((const float4*)W2)[idx];
    }
    if (tid < 128) {
        int row = row0 + tid;
        batchS[tid] = (row < N_NODESC) ? batch[row] : -1;
    }

    // agg8: 2 threads per row, float4 each
    {
        int row_l = tid >> 1, half = tid & 1;
        int row = row0 + row_l;
        float4 acc = make_float4(0.f, 0.f, 0.f, 0.f);
        if (row < N_NODESC) {
            const float4* x4 = (const float4*)x;
            acc = x4[row * 2 + half];
            int s0 = g_off[row], s1 = g_off[row + 1];
            for (int j = s0; j < s1; j++) {
                float4 v = x4[g_srcs[j] * 2 + half];
                acc.x += v.x; acc.y += v.y; acc.z += v.z; acc.w += v.w;
            }
        }
        *(float4*)&A8[row_l * 8 + half * 4] = acc;
    }
    __syncthreads();

    int tx = tid & 15, ty = tid >> 4;
    int r0 = ty * 8, c0 = tx * 4;

    // GEMM1 (K=8): mid = relu(agg8 @ W1 + b1) -> As (distinct region, no sync hazard)
    ull acc[8][4];
    #pragma unroll
    for (int i = 0; i < 8; i++)
        #pragma unroll
        for (int j = 0; j < 4; j++) acc[i][j] = 0ull;
    gemm_tile(A8, 8, B8, 8, acc, r0, c0);
    #pragma unroll
    for (int i = 0; i < 8; i++) {
        float4 lo, hi;
        epi_relu(acc[i], b1v, c0, lo, hi);
        *(float4*)&As[(r0 + i) * ASTRIDE + c0] = lo;
        *(float4*)&As[(r0 + i) * ASTRIDE + c0 + 64] = hi;
    }
    __syncthreads();

    // GEMM2: h1 = relu(mid @ W2 + b2)
    #pragma unroll
    for (int i = 0; i < 8; i++)
        #pragma unroll
        for (int j = 0; j < 4; j++) acc[i][j] = 0ull;
    gemm_tile(As, ASTRIDE, B2s, 128, acc, r0, c0);
    __syncthreads();
    #pragma unroll
    for (int i = 0; i < 8; i++) {
        float4 lo, hi;
        epi_relu(acc[i], b2v, c0, lo, hi);
        int rr = r0 + i, row = row0 + rr;
        *(float4*)&As[rr * ASTRIDE + c0] = lo;
        *(float4*)&As[rr * ASTRIDE + c0 + 64] = hi;
        if (row < N_NODESC) {
            *(float4*)&hout[row * HC + c0] = lo;
            *(float4*)&hout[row * HC + c0 + 64] = hi;
        }
    }
    __syncthreads();

    pool_tile(As, batchS, 0, tid);
}

// ---------------- classifier ----------------
__global__ void k_cls(const float* __restrict__ W1, const float* __restrict__ b1,
                      const float* __restrict__ bng, const float* __restrict__ bnb,
                      const float* __restrict__ bnm, const float* __restrict__ bnv,
                      const float* __restrict__ W2, const float* __restrict__ b2,
                      float* __restrict__ out) {
    __shared__ float ps[3 * HC];
    __shared__ float zs[2 * HC];
    int gph = blockIdx.x, tid = threadIdx.x;   // 256 threads
    for (int i = tid; i < 3 * HC; i += 256) ps[i] = g_pooled[gph * (3 * HC) + i];
    __syncthreads();
    float acc = b1[tid];
    for (int k = 0; k < 3 * HC; k++) acc += ps[k] * W1[k * 256 + tid];
    acc = (acc - bnm[tid]) * rsqrtf(bnv[tid] + 1e-5f) * bng[tid] + bnb[tid];
    acc = fmaxf(acc, 0.f);
    zs[tid] = acc;
    __syncthreads();
    if (tid < 4) {
        float s = b2[tid];
        for (int k = 0; k < 256; k++) s += zs[k] * W2[k * 4 + tid];
        out[gph * 4 + tid] = s;
    }
}

// ---------------- launch ----------------
extern "C" void kernel_launch(void* const* d_in, const int* in_sizes, int n_in,
                              void* d_out, int out_size) {
    const float* x   = (const float*)d_in[0];
    const int* ei    = (const int*)d_in[1];
    const int* batch = (const int*)d_in[2];
    const float* l1W1 = (const float*)d_in[3];
    const float* l1b1 = (const float*)d_in[4];
    const float* l1W2 = (const float*)d_in[5];
    const float* l1b2 = (const float*)d_in[6];
    const float* l2W1 = (const float*)d_in[7];
    const float* l2b1 = (const float*)d_in[8];
    const float* l2W2 = (const float*)d_in[9];
    const float* l2b2 = (const float*)d_in[10];
    const float* l3W1 = (const float*)d_in[11];
    const float* l3b1 = (const float*)d_in[12];
    const float* l3W2 = (const float*)d_in[13];
    const float* l3b2 = (const float*)d_in[14];
    const float* cW1  = (const float*)d_in[15];
    const float* cb1  = (const float*)d_in[16];
    const float* bng  = (const float*)d_in[17];
    const float* bnb  = (const float*)d_in[18];
    const float* bnm  = (const float*)d_in[19];
    const float* bnv  = (const float*)d_in[20];
    const float* cW2  = (const float*)d_in[21];
    const float* cb2  = (const float*)d_in[22];
    float* out = (float*)d_out;

    float *h1, *h2;
    cudaGetSymbolAddress((void**)&h1, g_h1);
    cudaGetSymbolAddress((void**)&h2, g_h2);

    const int LAYER_SMEM  = (128 * ASTRIDE + 2 * 128 * 128) * 4;         // 198656 B
    const int LAYER1_SMEM = (128 * ASTRIDE + 128 * 128 + 128 * 8 + 8 * 128) * 4; // 141312 B
    cudaFuncSetAttribute(k_layer,  cudaFuncAttributeMaxDynamicSharedMemorySize, LAYER_SMEM);
    cudaFuncSetAttribute(k_layer1, cudaFuncAttributeMaxDynamicSharedMemorySize, LAYER1_SMEM);

    const int blocks = (N_NODESC + 127) / 128;   // 391

    // CSR build
    k_init<<<(N_NODESC + 255) / 256, 256>>>();
    k_hist<<<(N_EDGESC + 255) / 256, 256>>>(ei);
    k_scan<<<1, 1024>>>();
    k_fill<<<(N_EDGESC + 255) / 256, 256>>>(ei);

    // fused layers (pooling accumulated in-kernel)
    k_layer1<<<blocks, 256, LAYER1_SMEM>>>(x, l1W1, l1b1, l1W2, l1b2, h1, batch);
    k_layer<<<blocks, 256, LAYER_SMEM>>>(h1, l2W1, l2b1, l2W2, l2b2, h2, batch, 1, 1);
    k_layer<<<blocks, 256, LAYER_SMEM>>>(h2, l3W1, l3b1, l3W2, l3b2, h2, batch, 2, 0);

    // classifier
    k_cls<<<N_GRAPHSC, 256>>>(cW1, cb1, bng, bnb, bnm, bnv, cW2, cb2, out);
}